// round 2
// baseline (speedup 1.0000x reference)
#include <cuda_runtime.h>
#include <cuda_fp16.h>

// ---------------------------------------------------------------------------
// m16n8k16 f16 MMA (f32 accum) — portable sm_80+ path (compute_103 base ok)
// ---------------------------------------------------------------------------
__device__ __forceinline__ void mma16816(float* d, const unsigned* a,
                                         const unsigned* b, const float* c) {
    asm volatile(
        "mma.sync.aligned.m16n8k16.row.col.f32.f16.f16.f32 "
        "{%0,%1,%2,%3}, {%4,%5,%6,%7}, {%8,%9}, {%10,%11,%12,%13};"
        : "=f"(d[0]), "=f"(d[1]), "=f"(d[2]), "=f"(d[3])
        : "r"(a[0]), "r"(a[1]), "r"(a[2]), "r"(a[3]),
          "r"(b[0]), "r"(b[1]),
          "f"(c[0]), "f"(c[1]), "f"(c[2]), "f"(c[3]));
}

__device__ __forceinline__ void ldmat4(unsigned* a, unsigned addr) {
    asm volatile(
        "ldmatrix.sync.aligned.m8n8.x4.shared.b16 {%0,%1,%2,%3}, [%4];"
        : "=r"(a[0]), "=r"(a[1]), "=r"(a[2]), "=r"(a[3]) : "r"(addr));
}

__device__ __forceinline__ unsigned smem_u32(const void* p) {
    unsigned a;
    asm("{ .reg .u64 t; cvta.to.shared.u64 t, %1; cvt.u32.u64 %0, t; }"
        : "=r"(a) : "l"(p));
    return a;
}

__device__ __forceinline__ __half2 tanh2(__half2 x) {
    unsigned xi = *reinterpret_cast<unsigned*>(&x), yi;
    asm("tanh.approx.f16x2 %0, %1;" : "=r"(yi) : "r"(xi));
    return *reinterpret_cast<__half2*>(&yi);
}
__device__ __forceinline__ __half2 sig2(__half2 x) {
    const __half2 h05 = __float2half2_rn(0.5f);
    return __hfma2(tanh2(__hmul2(x, h05)), h05, h05);
}
__device__ __forceinline__ unsigned pack2(float lo, float hi) {
    __half2 h = __floats2half2_rn(lo, hi);
    return *reinterpret_cast<unsigned*>(&h);
}

// ---------------------------------------------------------------------------
// Fused LSTM: one CTA per 128 batch rows, 512 threads (16 warps).
// Per step: D[128 x 128] = A[128 x 48] * B[48 x 128] via 24 HMMA/warp.
//   A = [h(32 f16) | x0,x1,x2,1 | 0-pad], double-buffered h in SMEM.
//   B = [W_hh | W_ih | b_ih+b_hh] cols n = g*32+u, resident in registers.
// Warp (wm = w%8, wn = w/8): rows 16*wm..+15, units 16*wn..+15, all 4 gates.
// Thread holds all 4 gates of its units -> c/h update fully local.
// ---------------------------------------------------------------------------
__global__ void __launch_bounds__(512, 1) lstm_fused(
    const float* __restrict__ x,
    const int* __restrict__ mat_idx, const int* __restrict__ freq_idx,
    const float* __restrict__ W_ih, const float* __restrict__ W_hh,
    const float* __restrict__ b_ih, const float* __restrict__ b_hh,
    const float* __restrict__ mat_emb, const float* __restrict__ freq_emb,
    const float* __restrict__ fc_w, const float* __restrict__ fc_b,
    float* __restrict__ out, int T)
{
    constexpr int HS = 40;                    // h SMEM stride (halves), pad vs 32
    __shared__ __half s_h[2][128][HS];        // double-buffered hidden state

    const int tid  = threadIdx.x;
    const int wid  = tid >> 5, lane = tid & 31;
    const int wm   = wid & 7;                 // row tile (16 rows)
    const int wn   = wid >> 3;                // unit tile (16 units)
    const int q    = lane & 3;                // thread-in-group
    const int gid  = lane >> 2;               // group id (0..7)

    const int r0l  = 16 * wm + gid;           // local row (and +8)
    const long long r0 = (long long)blockIdx.x * 128 + r0l;
    const long long r1 = r0 + 8;

    // ---- stationary B fragments in registers: bf[nt][kc][2] ----
    // nt = g*2 + b : gate g (i,f,g,o), unit block b (units 8b..8b+7 of tile)
    unsigned bf[8][3][2];
#pragma unroll
    for (int nt = 0; nt < 8; ++nt) {
        int g = nt >> 1, b = nt & 1;
        int n = g * 32 + 16 * wn + 8 * b + gid;     // weight row = gate col
#pragma unroll
        for (int kc = 0; kc < 3; ++kc) {
#pragma unroll
            for (int rr = 0; rr < 2; ++rr) {
                int k0 = kc * 16 + 2 * q + 8 * rr;
                float v0 = 0.f, v1 = 0.f;
                if (k0 < 32)       v0 = W_hh[n * 32 + k0];
                else if (k0 < 35)  v0 = W_ih[n * 3 + (k0 - 32)];
                else if (k0 == 35) v0 = b_ih[n] + b_hh[n];
                int k1 = k0 + 1;
                if (k1 < 32)       v1 = W_hh[n * 32 + k1];
                else if (k1 < 35)  v1 = W_ih[n * 3 + (k1 - 32)];
                else if (k1 == 35) v1 = b_ih[n] + b_hh[n];
                bf[nt][kc][rr] = pack2(v0, v1);
            }
        }
    }

    // ---- ldmatrix source addresses (both buffers, both k-chunks) ----
    // lane l: matrix m=l/8: row_off = (l&7) + ((l>>3)&1)*8, col_off = (l>>4)*8
    const int row_off = (lane & 7) + ((lane >> 3) & 1) * 8;
    const int col_off = (lane >> 4) * 8;
    unsigned lmaddr[2][2];
#pragma unroll
    for (int bu = 0; bu < 2; ++bu)
#pragma unroll
        for (int kc = 0; kc < 2; ++kc)
            lmaddr[bu][kc] =
                smem_u32(&s_h[bu][16 * wm + row_off][16 * kc + col_off]);

    // ---- h write addresses: rows r0l, r0l+8; unit cols per b ----
    __half2* stp[2][2];
#pragma unroll
    for (int rs = 0; rs < 2; ++rs)
#pragma unroll
        for (int b = 0; b < 2; ++b)
            stp[rs][b] = reinterpret_cast<__half2*>(
                &s_h[0][r0l + 8 * rs][16 * wn + 8 * b + 2 * q]);
    const int bufstride2 = (128 * HS) / 2;    // __half2 elements per buffer

    // ---- zero h buffer 1 (read at t=0) ----
    {
        unsigned* z = reinterpret_cast<unsigned*>(&s_h[1][0][0]);
        for (int i = tid; i < 128 * HS / 2; i += 512) z[i] = 0u;
    }

    // ---- x prefetch (t = 0) ----
    const float* px0 = x + (size_t)r0 * T * 3;
    const float* px1 = x + (size_t)r1 * T * 3;
    float cx0 = 0.f, cx1 = 0.f, cx2 = 0.f, cx3 = 0.f;
    if (q == 0) { cx0 = px0[0]; cx1 = px0[1]; cx2 = px1[0]; cx3 = px1[1]; }
    else if (q == 1) { cx0 = px0[2]; cx2 = px1[2]; }

    float c[8];
#pragma unroll
    for (int i = 0; i < 8; ++i) c[i] = 0.f;
    const float zc[4] = {0.f, 0.f, 0.f, 0.f};
    const __half2 h05 = __float2half2_rn(0.5f);

    __syncthreads();

    for (int t = 0; t < T; ++t) {
        const int rb = (t + 1) & 1;           // read h(t-1)
        const int wb = t & 1;                 // write h(t)

        // A fragments: chunks 0,1 = h from SMEM; chunk 2 = x in registers
        unsigned a0[4], a1[4], a2[4];
        ldmat4(a0, lmaddr[rb][0]);
        ldmat4(a1, lmaddr[rb][1]);
        a2[2] = a2[3] = 0u;
        if (q == 0)      { a2[0] = pack2(cx0, cx1); a2[1] = pack2(cx2, cx3); }
        else if (q == 1) { a2[0] = pack2(cx0, 1.f); a2[1] = pack2(cx2, 1.f); }
        else             { a2[0] = a2[1] = 0u; }

        // prefetch x(t+1)
        if (t + 1 < T) {
            const float* p0 = px0 + (size_t)(t + 1) * 3;
            const float* p1 = px1 + (size_t)(t + 1) * 3;
            if (q == 0) { cx0 = p0[0]; cx1 = p0[1]; cx2 = p1[0]; cx3 = p1[1]; }
            else if (q == 1) { cx0 = p0[2]; cx2 = p1[2]; }
        }

        // ---- 24 MMAs ----
        float acc[8][4];
#pragma unroll
        for (int nt = 0; nt < 8; ++nt) mma16816(acc[nt], a0, bf[nt][0], zc);
#pragma unroll
        for (int nt = 0; nt < 8; ++nt) mma16816(acc[nt], a1, bf[nt][1], acc[nt]);
#pragma unroll
        for (int nt = 0; nt < 8; ++nt) mma16816(acc[nt], a2, bf[nt][2], acc[nt]);

        // ---- activations + state update (all 4 gates local) ----
#pragma unroll
        for (int b = 0; b < 2; ++b) {
            __half2 hh[2];
#pragma unroll
            for (int j = 0; j < 2; ++j) {
                __half2 pi = __floats2half2_rn(acc[0 + b][j], acc[0 + b][2 + j]);
                __half2 pf = __floats2half2_rn(acc[2 + b][j], acc[2 + b][2 + j]);
                __half2 pg = __floats2half2_rn(acc[4 + b][j], acc[4 + b][2 + j]);
                __half2 po = __floats2half2_rn(acc[6 + b][j], acc[6 + b][2 + j]);
                __half2 si = sig2(pi), sf = sig2(pf), so = sig2(po);
                __half2 tg = tanh2(pg);
                int ci = b * 4 + j * 2;
                float c0 = fmaf(__low2float(sf),  c[ci],
                                __low2float(si)  * __low2float(tg));
                float c1 = fmaf(__high2float(sf), c[ci + 1],
                                __high2float(si) * __high2float(tg));
                c[ci] = c0; c[ci + 1] = c1;
                __half2 tc = tanh2(__floats2half2_rn(c0, c1));
                hh[j] = __hmul2(so, tc);       // (h[r0], h[r1]) for unit u+j
            }
            // repack rows: (u, u+1) contiguous per row
            __half2 row0 = __lows2half2(hh[0], hh[1]);
            __half2 row1 = __highs2half2(hh[0], hh[1]);
            stp[0][b][wb * bufstride2] = row0;
            stp[1][b][wb * bufstride2] = row1;
        }
        __syncthreads();
    }

    // ---- fc head: out[b] = h_T . fc_w[0:32] + emb terms + fc_b ----
    const int wbl = (T - 1) & 1;
    if (tid < 128) {
        long long row = (long long)blockIdx.x * 128 + tid;
        float s = fc_b[0];
#pragma unroll
        for (int u = 0; u < 32; ++u)
            s += __half2float(s_h[wbl][tid][u]) * fc_w[u];
        int mi = mat_idx[row], fi = freq_idx[row];
#pragma unroll
        for (int e = 0; e < 4; ++e) s += mat_emb[mi * 4 + e] * fc_w[32 + e];
#pragma unroll
        for (int e = 0; e < 2; ++e) s += freq_emb[fi * 2 + e] * fc_w[36 + e];
        out[row] = s;
    }
}

extern "C" void kernel_launch(void* const* d_in, const int* in_sizes, int n_in,
                              void* d_out, int out_size) {
    const float* x        = (const float*)d_in[0];
    const int*   mat_idx  = (const int*)  d_in[1];
    const int*   freq_idx = (const int*)  d_in[2];
    const float* W_ih     = (const float*)d_in[3];
    const float* W_hh     = (const float*)d_in[4];
    const float* b_ih     = (const float*)d_in[5];
    const float* b_hh     = (const float*)d_in[6];
    const float* mat_emb  = (const float*)d_in[7];
    const float* freq_emb = (const float*)d_in[8];
    const float* fc_w     = (const float*)d_in[9];
    const float* fc_b     = (const float*)d_in[10];

    int B = in_sizes[1];                    // mat_idx has B elements
    int T = in_sizes[0] / (B * 3);          // x has B*T*3 elements
    int grid = B / 128;

    lstm_fused<<<grid, 512>>>(x, mat_idx, freq_idx, W_ih, W_hh, b_ih, b_hh,
                              mat_emb, freq_emb, fc_w, fc_b,
                              (float*)d_out, T);
}

// round 3
// speedup vs baseline: 1.3243x; 1.3243x over previous
#include <cuda_runtime.h>
#include <cuda_fp16.h>

// ---------------------------------------------------------------------------
// m16n8k16 f16 MMA (f32 accum) — portable sm_80+ path (compute_103 base ok)
// ---------------------------------------------------------------------------
__device__ __forceinline__ void mma16816(float* d, const unsigned* a,
                                         const unsigned* b, const float* c) {
    asm volatile(
        "mma.sync.aligned.m16n8k16.row.col.f32.f16.f16.f32 "
        "{%0,%1,%2,%3}, {%4,%5,%6,%7}, {%8,%9}, {%10,%11,%12,%13};"
        : "=f"(d[0]), "=f"(d[1]), "=f"(d[2]), "=f"(d[3])
        : "r"(a[0]), "r"(a[1]), "r"(a[2]), "r"(a[3]),
          "r"(b[0]), "r"(b[1]),
          "f"(c[0]), "f"(c[1]), "f"(c[2]), "f"(c[3]));
}

__device__ __forceinline__ void ldmat4(unsigned* a, unsigned addr) {
    asm volatile(
        "ldmatrix.sync.aligned.m8n8.x4.shared.b16 {%0,%1,%2,%3}, [%4];"
        : "=r"(a[0]), "=r"(a[1]), "=r"(a[2]), "=r"(a[3]) : "r"(addr));
}

__device__ __forceinline__ unsigned smem_u32(const void* p) {
    unsigned a;
    asm("{ .reg .u64 t; cvta.to.shared.u64 t, %1; cvt.u32.u64 %0, t; }"
        : "=r"(a) : "l"(p));
    return a;
}

__device__ __forceinline__ __half2 tanh2(__half2 x) {
    unsigned xi = *reinterpret_cast<unsigned*>(&x), yi;
    asm("tanh.approx.f16x2 %0, %1;" : "=r"(yi) : "r"(xi));
    return *reinterpret_cast<__half2*>(&yi);
}
__device__ __forceinline__ __half2 sig2(__half2 x) {
    const __half2 h05 = __float2half2_rn(0.5f);
    return __hfma2(tanh2(__hmul2(x, h05)), h05, h05);
}
__device__ __forceinline__ unsigned pack2(float lo, float hi) {
    __half2 h = __floats2half2_rn(lo, hi);
    return *reinterpret_cast<unsigned*>(&h);
}

// pair-scoped named barrier: 2 warps (64 threads), ids 1..2
__device__ __forceinline__ void bar_pair(int id) {
    asm volatile("bar.sync %0, 64;" :: "r"(id) : "memory");
}

// ---------------------------------------------------------------------------
// Fused LSTM: one CTA per 32 batch rows, 128 threads (4 warps), 4 CTAs/SM.
// Per step: D[32 x 128] = A[32 x 48] * B[48 x 128], 24 HMMA/warp.
//   A = [h(32 f16) | x0,x1,x2,1 | 0-pad], double-buffered h in SMEM.
//   B = [W_hh | W_ih | b_ih+b_hh] cols n = g*32+u, resident in registers.
// Warp (wm = wid&1, wn = wid>>1): rows 16*wm..+15, units 16*wn..+15, 4 gates.
// Sync scope: only the 2 warps sharing a row tile (named barrier id 1+wm).
// ---------------------------------------------------------------------------
__global__ void __launch_bounds__(128, 4) lstm_fused(
    const float* __restrict__ x,
    const int* __restrict__ mat_idx, const int* __restrict__ freq_idx,
    const float* __restrict__ W_ih, const float* __restrict__ W_hh,
    const float* __restrict__ b_ih, const float* __restrict__ b_hh,
    const float* __restrict__ mat_emb, const float* __restrict__ freq_emb,
    const float* __restrict__ fc_w, const float* __restrict__ fc_b,
    float* __restrict__ out, int T)
{
    constexpr int ROWS = 32;                  // batch rows per CTA
    constexpr int HS = 40;                    // h SMEM stride (halves), padded
    __shared__ __half s_h[2][ROWS][HS];       // double-buffered hidden state

    const int tid  = threadIdx.x;
    const int wid  = tid >> 5, lane = tid & 31;
    const int wm   = wid & 1;                 // row tile (16 rows)
    const int wn   = wid >> 1;                // unit tile (16 units)
    const int q    = lane & 3;                // thread-in-group
    const int gid  = lane >> 2;               // group id (0..7)

    const int r0l  = 16 * wm + gid;           // local row (and +8)
    const long long r0 = (long long)blockIdx.x * ROWS + r0l;
    const long long r1 = r0 + 8;

    // ---- stationary B fragments in registers: bf[nt][kc][2] ----
    // nt = g*2 + b : gate g (i,f,g,o), unit block b (units 8b..8b+7 of tile)
    unsigned bf[8][3][2];
#pragma unroll
    for (int nt = 0; nt < 8; ++nt) {
        int g = nt >> 1, b = nt & 1;
        int n = g * 32 + 16 * wn + 8 * b + gid;     // weight row = gate col
#pragma unroll
        for (int kc = 0; kc < 3; ++kc) {
#pragma unroll
            for (int rr = 0; rr < 2; ++rr) {
                int k0 = kc * 16 + 2 * q + 8 * rr;
                float v0 = 0.f, v1 = 0.f;
                if (k0 < 32)       v0 = W_hh[n * 32 + k0];
                else if (k0 < 35)  v0 = W_ih[n * 3 + (k0 - 32)];
                else if (k0 == 35) v0 = b_ih[n] + b_hh[n];
                int k1 = k0 + 1;
                if (k1 < 32)       v1 = W_hh[n * 32 + k1];
                else if (k1 < 35)  v1 = W_ih[n * 3 + (k1 - 32)];
                else if (k1 == 35) v1 = b_ih[n] + b_hh[n];
                bf[nt][kc][rr] = pack2(v0, v1);
            }
        }
    }

    // ---- ldmatrix source addresses (both buffers, both k-chunks) ----
    const int row_off = (lane & 7) + ((lane >> 3) & 1) * 8;
    const int col_off = (lane >> 4) * 8;
    unsigned lmaddr[2][2];
#pragma unroll
    for (int bu = 0; bu < 2; ++bu)
#pragma unroll
        for (int kc = 0; kc < 2; ++kc)
            lmaddr[bu][kc] =
                smem_u32(&s_h[bu][16 * wm + row_off][16 * kc + col_off]);

    // ---- h write addresses: rows r0l, r0l+8; unit cols per b ----
    __half2* stp[2][2];
#pragma unroll
    for (int rs = 0; rs < 2; ++rs)
#pragma unroll
        for (int b = 0; b < 2; ++b)
            stp[rs][b] = reinterpret_cast<__half2*>(
                &s_h[0][r0l + 8 * rs][16 * wn + 8 * b + 2 * q]);
    const int bufstride2 = (ROWS * HS) / 2;   // __half2 elements per buffer

    // ---- zero h buffer 1 (read at t=0) ----
    {
        unsigned* z = reinterpret_cast<unsigned*>(&s_h[1][0][0]);
        for (int i = tid; i < ROWS * HS / 2; i += 128) z[i] = 0u;
    }

    // ---- x prefetch (t = 0) ----
    const float* px0 = x + (size_t)r0 * T * 3;
    const float* px1 = x + (size_t)r1 * T * 3;
    float cx0 = 0.f, cx1 = 0.f, cx2 = 0.f, cx3 = 0.f;
    if (q == 0) { cx0 = px0[0]; cx1 = px0[1]; cx2 = px1[0]; cx3 = px1[1]; }
    else if (q == 1) { cx0 = px0[2]; cx2 = px1[2]; }

    float c[8];
#pragma unroll
    for (int i = 0; i < 8; ++i) c[i] = 0.f;
    const float zc[4] = {0.f, 0.f, 0.f, 0.f};
    const int barid = 1 + wm;

    __syncthreads();

    for (int t = 0; t < T; ++t) {
        const int rb = (t + 1) & 1;           // read h(t-1)
        const int wb = t & 1;                 // write h(t)

        // A fragments: chunks 0,1 = h from SMEM; chunk 2 = x in registers
        unsigned a0[4], a1[4], a2[4];
        ldmat4(a0, lmaddr[rb][0]);
        ldmat4(a1, lmaddr[rb][1]);
        a2[2] = a2[3] = 0u;
        if (q == 0)      { a2[0] = pack2(cx0, cx1); a2[1] = pack2(cx2, cx3); }
        else if (q == 1) { a2[0] = pack2(cx0, 1.f); a2[1] = pack2(cx2, 1.f); }
        else             { a2[0] = a2[1] = 0u; }

        // prefetch x(t+1)
        if (t + 1 < T) {
            const float* p0 = px0 + (size_t)(t + 1) * 3;
            const float* p1 = px1 + (size_t)(t + 1) * 3;
            if (q == 0) { cx0 = p0[0]; cx1 = p0[1]; cx2 = p1[0]; cx3 = p1[1]; }
            else if (q == 1) { cx0 = p0[2]; cx2 = p1[2]; }
        }

        // ---- 24 MMAs ----
        float acc[8][4];
#pragma unroll
        for (int nt = 0; nt < 8; ++nt) mma16816(acc[nt], a0, bf[nt][0], zc);
#pragma unroll
        for (int nt = 0; nt < 8; ++nt) mma16816(acc[nt], a1, bf[nt][1], acc[nt]);
#pragma unroll
        for (int nt = 0; nt < 8; ++nt) mma16816(acc[nt], a2, bf[nt][2], acc[nt]);

        // ---- activations + state update (all 4 gates local) ----
#pragma unroll
        for (int b = 0; b < 2; ++b) {
            __half2 hh[2];
#pragma unroll
            for (int j = 0; j < 2; ++j) {
                __half2 pi = __floats2half2_rn(acc[0 + b][j], acc[0 + b][2 + j]);
                __half2 pf = __floats2half2_rn(acc[2 + b][j], acc[2 + b][2 + j]);
                __half2 pg = __floats2half2_rn(acc[4 + b][j], acc[4 + b][2 + j]);
                __half2 po = __floats2half2_rn(acc[6 + b][j], acc[6 + b][2 + j]);
                __half2 si = sig2(pi), sf = sig2(pf), so = sig2(po);
                __half2 tg = tanh2(pg);
                int ci = b * 4 + j * 2;
                float c0 = fmaf(__low2float(sf),  c[ci],
                                __low2float(si)  * __low2float(tg));
                float c1 = fmaf(__high2float(sf), c[ci + 1],
                                __high2float(si) * __high2float(tg));
                c[ci] = c0; c[ci + 1] = c1;
                __half2 tc = tanh2(__floats2half2_rn(c0, c1));
                hh[j] = __hmul2(so, tc);       // (h[r0], h[r1]) for unit u+j
            }
            // repack rows: (u, u+1) contiguous per row
            __half2 row0 = __lows2half2(hh[0], hh[1]);
            __half2 row1 = __highs2half2(hh[0], hh[1]);
            stp[0][b][wb * bufstride2] = row0;
            stp[1][b][wb * bufstride2] = row1;
        }
        // sync only the two warps sharing this row tile
        bar_pair(barid);
    }

    __syncthreads();

    // ---- fc head: out[b] = h_T . fc_w[0:32] + emb terms + fc_b ----
    const int wbl = (T - 1) & 1;
    if (tid < ROWS) {
        long long row = (long long)blockIdx.x * ROWS + tid;
        float s = fc_b[0];
#pragma unroll
        for (int u = 0; u < 32; ++u)
            s += __half2float(s_h[wbl][tid][u]) * fc_w[u];
        int mi = mat_idx[row], fi = freq_idx[row];
#pragma unroll
        for (int e = 0; e < 4; ++e) s += mat_emb[mi * 4 + e] * fc_w[32 + e];
#pragma unroll
        for (int e = 0; e < 2; ++e) s += freq_emb[fi * 2 + e] * fc_w[36 + e];
        out[row] = s;
    }
}

extern "C" void kernel_launch(void* const* d_in, const int* in_sizes, int n_in,
                              void* d_out, int out_size) {
    const float* x        = (const float*)d_in[0];
    const int*   mat_idx  = (const int*)  d_in[1];
    const int*   freq_idx = (const int*)  d_in[2];
    const float* W_ih     = (const float*)d_in[3];
    const float* W_hh     = (const float*)d_in[4];
    const float* b_ih     = (const float*)d_in[5];
    const float* b_hh     = (const float*)d_in[6];
    const float* mat_emb  = (const float*)d_in[7];
    const float* freq_emb = (const float*)d_in[8];
    const float* fc_w     = (const float*)d_in[9];
    const float* fc_b     = (const float*)d_in[10];

    int B = in_sizes[1];                    // mat_idx has B elements
    int T = in_sizes[0] / (B * 3);          // x has B*T*3 elements
    int grid = B / 32;                      // 32 rows per CTA

    lstm_fused<<<grid, 128>>>(x, mat_idx, freq_idx, W_ih, W_hh, b_ih, b_hh,
                              mat_emb, freq_emb, fc_w, fc_b,
                              (float*)d_out, T);
}

// round 4
// speedup vs baseline: 1.3928x; 1.0517x over previous
#include <cuda_runtime.h>
#include <cuda_fp16.h>

// ---------------------------------------------------------------------------
// mma / movmatrix wrappers (portable sm_80+/sm_75+, fine on compute_103 base)
// ---------------------------------------------------------------------------
__device__ __forceinline__ void mma16816(float* d, const unsigned* a,
                                         unsigned b0, unsigned b1,
                                         const float* c) {
    asm volatile(
        "mma.sync.aligned.m16n8k16.row.col.f32.f16.f16.f32 "
        "{%0,%1,%2,%3}, {%4,%5,%6,%7}, {%8,%9}, {%10,%11,%12,%13};"
        : "=f"(d[0]), "=f"(d[1]), "=f"(d[2]), "=f"(d[3])
        : "r"(a[0]), "r"(a[1]), "r"(a[2]), "r"(a[3]),
          "r"(b0), "r"(b1),
          "f"(c[0]), "f"(c[1]), "f"(c[2]), "f"(c[3]));
}
__device__ __forceinline__ void mma1688(float* d, const unsigned* a,
                                        unsigned b0, const float* c) {
    asm volatile(
        "mma.sync.aligned.m16n8k8.row.col.f32.f16.f16.f32 "
        "{%0,%1,%2,%3}, {%4,%5}, {%6}, {%7,%8,%9,%10};"
        : "=f"(d[0]), "=f"(d[1]), "=f"(d[2]), "=f"(d[3])
        : "r"(a[0]), "r"(a[1]), "r"(b0),
          "f"(c[0]), "f"(c[1]), "f"(c[2]), "f"(c[3]));
}
__device__ __forceinline__ unsigned movmt(unsigned a) {
    unsigned d;
    asm("movmatrix.sync.aligned.m8n8.trans.b16 %0, %1;" : "=r"(d) : "r"(a));
    return d;
}
__device__ __forceinline__ __half2 tanh2(__half2 x) {
    unsigned xi = *reinterpret_cast<unsigned*>(&x), yi;
    asm("tanh.approx.f16x2 %0, %1;" : "=r"(yi) : "r"(xi));
    return *reinterpret_cast<__half2*>(&yi);
}
__device__ __forceinline__ __half2 sig2(__half2 x) {
    const __half2 h05 = __float2half2_rn(0.5f);
    return __hfma2(tanh2(__hmul2(x, h05)), h05, h05);
}
__device__ __forceinline__ unsigned pack2(float lo, float hi) {
    __half2 h = __floats2half2_rn(lo, hi);
    return *reinterpret_cast<unsigned*>(&h);
}

// ---------------------------------------------------------------------------
// Warp-autonomous fused LSTM.
// Warp owns 8 batch rows for the entire sequence. Per step:
//   D[128 gates x 8 rows] = A[128 x 48] (weights, registers) * B[48 x 8] (state)
//   A rows n = g*32 + u (gate-major), 8 m-tiles; k = [W_hh(32) | x0,x1,x2,1(k8)]
//   B = [h(32) | x,1(8)]; h fragments rebuilt each step via 4x movmatrix.trans.
// No SMEM, no barriers, no cross-warp traffic in the recurrence.
// ---------------------------------------------------------------------------
__global__ void __launch_bounds__(64, 7) lstm_fused(
    const float* __restrict__ x,
    const int* __restrict__ mat_idx, const int* __restrict__ freq_idx,
    const float* __restrict__ W_ih, const float* __restrict__ W_hh,
    const float* __restrict__ b_ih, const float* __restrict__ b_hh,
    const float* __restrict__ mat_emb, const float* __restrict__ freq_emb,
    const float* __restrict__ fc_w, const float* __restrict__ fc_b,
    float* __restrict__ out, int T)
{
    const int tid  = threadIdx.x;
    const int wid  = tid >> 5, lane = tid & 31;
    const int q    = lane & 3;            // col-pair selector
    const int gid  = lane >> 2;           // row-in-tile / batch col

    const long long rowbase = ((long long)blockIdx.x * 2 + wid) * 8;

    // ---- stationary A fragments (weights), W'(n,k):
    //   k<32 -> W_hh[n][k]; k in 32..34 -> W_ih[n][k-32]; k==35 -> bias; else 0
    auto wval = [&](int n, int k) -> float {
        if (k < 32)  return W_hh[n * 32 + k];
        if (k < 35)  return W_ih[n * 3 + (k - 32)];
        if (k == 35) return b_ih[n] + b_hh[n];
        return 0.f;
    };
    unsigned af[8][2][4];   // m-tile, k-chunk(0,1), frag
    unsigned af2[8][2];     // k-chunk 2 as m16n8k8
#pragma unroll
    for (int mt = 0; mt < 8; ++mt) {
        int n0 = 16 * mt + gid, n1 = n0 + 8;
#pragma unroll
        for (int kc = 0; kc < 2; ++kc) {
            int k0 = 16 * kc + 2 * q;
            af[mt][kc][0] = pack2(wval(n0, k0),     wval(n0, k0 + 1));
            af[mt][kc][1] = pack2(wval(n1, k0),     wval(n1, k0 + 1));
            af[mt][kc][2] = pack2(wval(n0, k0 + 8), wval(n0, k0 + 9));
            af[mt][kc][3] = pack2(wval(n1, k0 + 8), wval(n1, k0 + 9));
        }
        int k2 = 32 + 2 * q;
        af2[mt][0] = pack2(wval(n0, k2), wval(n0, k2 + 1));
        af2[mt][1] = pack2(wval(n1, k2), wval(n1, k2 + 1));
    }

    // ---- x stream for batch row rowbase+gid (lanes q=0/1 load) ----
    const float* pxr = x + (size_t)(rowbase + gid) * T * 3;
    float xp0 = 0.f, xp1 = 0.f, xp2 = 0.f;
    if (q == 0) { xp0 = pxr[0]; xp1 = pxr[1]; }
    else if (q == 1) { xp2 = pxr[2]; }

    // ---- loop-carried state ----
    unsigned b00 = 0, b01 = 0, b10 = 0, b11 = 0;   // h fragments (t=0: h=0)
    __half2 cst[4];
#pragma unroll
    for (int s = 0; s < 4; ++s) cst[s] = __float2half2_rn(0.f);
    const float zc[4] = {0.f, 0.f, 0.f, 0.f};
    unsigned hs[4];

    for (int t = 0; t < T; ++t) {
        // B chunk 2: (x0,x1 | x2,1 | 0) for batch row gid
        unsigned b2;
        if (q == 0)      b2 = pack2(xp0, xp1);
        else if (q == 1) b2 = pack2(xp2, 1.f);
        else             b2 = 0u;

        if (t + 1 < T) {   // prefetch next x under the MMAs
            const float* p = pxr + (size_t)(t + 1) * 3;
            if (q == 0) { xp0 = p[0]; xp1 = p[1]; }
            else if (q == 1) { xp2 = p[2]; }
        }

        // ---- 24 tensor ops: gates[128 x 8rows] (+bias, +x proj) ----
        float acc[8][4];
#pragma unroll
        for (int mt = 0; mt < 8; ++mt) mma16816(acc[mt], af[mt][0], b00, b01, zc);
#pragma unroll
        for (int mt = 0; mt < 8; ++mt) mma16816(acc[mt], af[mt][1], b10, b11, acc[mt]);
#pragma unroll
        for (int mt = 0; mt < 8; ++mt) mma1688(acc[mt], af2[mt], b2, acc[mt]);

        // ---- local LSTM update: s = unit slot {gid, gid+8, gid+16, gid+24} ----
#pragma unroll
        for (int half = 0; half < 2; ++half) {
#pragma unroll
            for (int rsel = 0; rsel < 2; ++rsel) {
                int s = half * 2 + rsel;
                int i0 = rsel * 2;
                __half2 pi = __floats2half2_rn(acc[0 + half][i0], acc[0 + half][i0 + 1]);
                __half2 pf = __floats2half2_rn(acc[2 + half][i0], acc[2 + half][i0 + 1]);
                __half2 pg = __floats2half2_rn(acc[4 + half][i0], acc[4 + half][i0 + 1]);
                __half2 po = __floats2half2_rn(acc[6 + half][i0], acc[6 + half][i0 + 1]);
                __half2 si = sig2(pi), sf = sig2(pf), so = sig2(po);
                __half2 tg = tanh2(pg);
                __half2 cc = __hfma2(sf, cst[s], __hmul2(si, tg));
                cst[s] = cc;
                __half2 hv = __hmul2(so, tanh2(cc));
                hs[s] = *reinterpret_cast<unsigned*>(&hv);
            }
        }

        // ---- rebuild B fragments for next step: register transpose ----
        // hs[s] = H[unit u_s][batch 2q:2q+1]; movmatrix -> H[u 2q:2q+1][batch gid]
        b00 = movmt(hs[0]);   // units 0-7   (s0: u=gid)
        b01 = movmt(hs[1]);   // units 8-15  (s1: u=gid+8)
        b10 = movmt(hs[2]);   // units 16-23
        b11 = movmt(hs[3]);   // units 24-31
    }

    // ---- fc head: out[r] = h_T . fc_w[0:32] + emb + fc_b ----
    float p_lo = 0.f, p_hi = 0.f;   // batch rows rowbase+2q, rowbase+2q+1
#pragma unroll
    for (int s = 0; s < 4; ++s) {
        __half2 hv = *reinterpret_cast<__half2*>(&hs[s]);
        float w = fc_w[8 * s + gid];
        p_lo = fmaf(__low2float(hv),  w, p_lo);
        p_hi = fmaf(__high2float(hv), w, p_hi);
    }
#pragma unroll
    for (int off = 4; off < 32; off <<= 1) {
        p_lo += __shfl_xor_sync(0xFFFFFFFFu, p_lo, off);
        p_hi += __shfl_xor_sync(0xFFFFFFFFu, p_hi, off);
    }
    if (lane < 4) {
        float base = fc_b[0];
#pragma unroll
        for (int k = 0; k < 2; ++k) {
            long long r = rowbase + 2 * q + k;
            float s = (k ? p_hi : p_lo) + base;
            int mi = mat_idx[r], fi = freq_idx[r];
#pragma unroll
            for (int e = 0; e < 4; ++e) s += mat_emb[mi * 4 + e] * fc_w[32 + e];
#pragma unroll
            for (int e = 0; e < 2; ++e) s += freq_emb[fi * 2 + e] * fc_w[36 + e];
            out[r] = s;
        }
    }
}

extern "C" void kernel_launch(void* const* d_in, const int* in_sizes, int n_in,
                              void* d_out, int out_size) {
    const float* x        = (const float*)d_in[0];
    const int*   mat_idx  = (const int*)  d_in[1];
    const int*   freq_idx = (const int*)  d_in[2];
    const float* W_ih     = (const float*)d_in[3];
    const float* W_hh     = (const float*)d_in[4];
    const float* b_ih     = (const float*)d_in[5];
    const float* b_hh     = (const float*)d_in[6];
    const float* mat_emb  = (const float*)d_in[7];
    const float* freq_emb = (const float*)d_in[8];
    const float* fc_w     = (const float*)d_in[9];
    const float* fc_b     = (const float*)d_in[10];

    int B = in_sizes[1];                  // mat_idx has B elements
    int T = in_sizes[0] / (B * 3);        // x has B*T*3 elements
    int grid = B / 16;                    // 16 rows per CTA (2 warps x 8 rows)

    lstm_fused<<<grid, 64>>>(x, mat_idx, freq_idx, W_ih, W_hh, b_ih, b_hh,
                             mat_emb, freq_emb, fc_w, fc_b,
                             (float*)d_out, T);
}

// round 5
// speedup vs baseline: 1.4222x; 1.0211x over previous
#include <cuda_runtime.h>
#include <cuda_fp16.h>

// ---------------------------------------------------------------------------
// f16-accumulate MMA + movmatrix wrappers (sm_75+/sm_80, fine on compute_103)
// ---------------------------------------------------------------------------
__device__ __forceinline__ void mmaf16_16816(unsigned* d, const unsigned* a,
                                             unsigned b0, unsigned b1,
                                             unsigned c0, unsigned c1) {
    asm volatile(
        "mma.sync.aligned.m16n8k16.row.col.f16.f16.f16.f16 "
        "{%0,%1}, {%2,%3,%4,%5}, {%6,%7}, {%8,%9};"
        : "=r"(d[0]), "=r"(d[1])
        : "r"(a[0]), "r"(a[1]), "r"(a[2]), "r"(a[3]),
          "r"(b0), "r"(b1), "r"(c0), "r"(c1));
}
__device__ __forceinline__ void mmaf16_1688(unsigned* d, const unsigned* a,
                                            unsigned b0,
                                            unsigned c0, unsigned c1) {
    asm volatile(
        "mma.sync.aligned.m16n8k8.row.col.f16.f16.f16.f16 "
        "{%0,%1}, {%2,%3}, {%4}, {%5,%6};"
        : "=r"(d[0]), "=r"(d[1])
        : "r"(a[0]), "r"(a[1]), "r"(b0), "r"(c0), "r"(c1));
}
__device__ __forceinline__ unsigned movmt(unsigned a) {
    unsigned d;
    asm("movmatrix.sync.aligned.m8n8.trans.b16 %0, %1;" : "=r"(d) : "r"(a));
    return d;
}
__device__ __forceinline__ __half2 tanh2(__half2 x) {
    unsigned xi = *reinterpret_cast<unsigned*>(&x), yi;
    asm("tanh.approx.f16x2 %0, %1;" : "=r"(yi) : "r"(xi));
    return *reinterpret_cast<__half2*>(&yi);
}
__device__ __forceinline__ __half2 sig2(__half2 x) {
    const __half2 h05 = __float2half2_rn(0.5f);
    return __hfma2(tanh2(__hmul2(x, h05)), h05, h05);
}
__device__ __forceinline__ unsigned pack2(float lo, float hi) {
    __half2 h = __floats2half2_rn(lo, hi);
    return *reinterpret_cast<unsigned*>(&h);
}
__device__ __forceinline__ __half2 u2h(unsigned u) {
    return *reinterpret_cast<__half2*>(&u);
}

// ---------------------------------------------------------------------------
// Warp-autonomous fused LSTM, full-f16 datapath.
// Warp owns 8 batch rows end-to-end. Per step:
//   D[128 gates x 8 rows] (f16) = A[128 x 48](weights, regs) * B[48 x 8](state)
//   A rows n = g*32 + u (gate-major); k = [W_hh(32) | x0,x1,x2,1 (k8)]
//   D fragments are already the half2 (unit, batch-pair) pairs the LSTM
//   update consumes -> zero conversions. h re-enters B via 4x movmatrix.
// No SMEM, no barriers, no cross-warp traffic.
// ---------------------------------------------------------------------------
__global__ void __launch_bounds__(64, 7) lstm_fused(
    const float* __restrict__ x,
    const int* __restrict__ mat_idx, const int* __restrict__ freq_idx,
    const float* __restrict__ W_ih, const float* __restrict__ W_hh,
    const float* __restrict__ b_ih, const float* __restrict__ b_hh,
    const float* __restrict__ mat_emb, const float* __restrict__ freq_emb,
    const float* __restrict__ fc_w, const float* __restrict__ fc_b,
    float* __restrict__ out, int T)
{
    const int tid  = threadIdx.x;
    const int wid  = tid >> 5, lane = tid & 31;
    const int q    = lane & 3;            // batch col-pair selector
    const int gid  = lane >> 2;           // row-in-tile

    const long long rowbase = ((long long)blockIdx.x * 2 + wid) * 8;

    // ---- stationary A fragments (weights) ----
    auto wval = [&](int n, int k) -> float {
        if (k < 32)  return W_hh[n * 32 + k];
        if (k < 35)  return W_ih[n * 3 + (k - 32)];
        if (k == 35) return b_ih[n] + b_hh[n];
        return 0.f;
    };
    unsigned af[8][2][4];   // m-tile, k16-chunk, frag
    unsigned af2[8][2];     // k8 chunk (x + bias)
#pragma unroll
    for (int mt = 0; mt < 8; ++mt) {
        int n0 = 16 * mt + gid, n1 = n0 + 8;
#pragma unroll
        for (int kc = 0; kc < 2; ++kc) {
            int k0 = 16 * kc + 2 * q;
            af[mt][kc][0] = pack2(wval(n0, k0),     wval(n0, k0 + 1));
            af[mt][kc][1] = pack2(wval(n1, k0),     wval(n1, k0 + 1));
            af[mt][kc][2] = pack2(wval(n0, k0 + 8), wval(n0, k0 + 9));
            af[mt][kc][3] = pack2(wval(n1, k0 + 8), wval(n1, k0 + 9));
        }
        int k2 = 32 + 2 * q;
        af2[mt][0] = pack2(wval(n0, k2), wval(n0, k2 + 1));
        af2[mt][1] = pack2(wval(n1, k2), wval(n1, k2 + 1));
    }

    // ---- x stream for batch row rowbase+gid (lanes q=0/1 carry data) ----
    const float* pxr = x + (size_t)(rowbase + gid) * T * 3;
    float xp0 = 0.f, xp1 = 0.f, xp2 = 0.f;
    if (q == 0) { xp0 = pxr[0]; xp1 = pxr[1]; }
    else if (q == 1) { xp2 = pxr[2]; }

    // ---- loop-carried state ----
    unsigned b00 = 0, b01 = 0, b10 = 0, b11 = 0;   // h fragments (t=0: h=0)
    __half2 cst[4];
#pragma unroll
    for (int s = 0; s < 4; ++s) cst[s] = __float2half2_rn(0.f);
    unsigned hs[4];

    for (int t = 0; t < T; ++t) {
        unsigned b2;
        if (q == 0)      b2 = pack2(xp0, xp1);
        else if (q == 1) b2 = pack2(xp2, 1.f);
        else             b2 = 0u;

        if (t + 1 < T) {   // prefetch next x under the MMAs
            const float* p = pxr + (size_t)(t + 1) * 3;
            if (q == 0) { xp0 = p[0]; xp1 = p[1]; }
            else if (q == 1) { xp2 = p[2]; }
        }

        // ---- 24 tensor ops, f16 accumulate ----
        unsigned acc[8][2];
#pragma unroll
        for (int mt = 0; mt < 8; ++mt)
            mmaf16_16816(acc[mt], af[mt][0], b00, b01, 0u, 0u);
#pragma unroll
        for (int mt = 0; mt < 8; ++mt)
            mmaf16_16816(acc[mt], af[mt][1], b10, b11, acc[mt][0], acc[mt][1]);
#pragma unroll
        for (int mt = 0; mt < 8; ++mt)
            mmaf16_1688(acc[mt], af2[mt], b2, acc[mt][0], acc[mt][1]);

        // ---- LSTM update; acc[2g+half][rsel] = gate g, unit 16half+8rsel+gid,
        //      batch cols {2q,2q+1} packed ----
#pragma unroll
        for (int half = 0; half < 2; ++half) {
#pragma unroll
            for (int rsel = 0; rsel < 2; ++rsel) {
                int s = half * 2 + rsel;
                __half2 si = sig2(u2h(acc[0 + half][rsel]));
                __half2 sf = sig2(u2h(acc[2 + half][rsel]));
                __half2 tg = tanh2(u2h(acc[4 + half][rsel]));
                __half2 so = sig2(u2h(acc[6 + half][rsel]));
                __half2 cc = __hfma2(sf, cst[s], __hmul2(si, tg));
                cst[s] = cc;
                __half2 hv = __hmul2(so, tanh2(cc));
                hs[s] = *reinterpret_cast<unsigned*>(&hv);
            }
        }

        // ---- rebuild B fragments for next step (register transpose) ----
        b00 = movmt(hs[0]);   // units 0-7
        b01 = movmt(hs[1]);   // units 8-15
        b10 = movmt(hs[2]);   // units 16-23
        b11 = movmt(hs[3]);   // units 24-31
    }

    // ---- fc head: out[r] = h_T . fc_w[0:32] + emb + fc_b ----
    float p_lo = 0.f, p_hi = 0.f;   // batch rows rowbase+2q, rowbase+2q+1
#pragma unroll
    for (int s = 0; s < 4; ++s) {
        __half2 hv = u2h(hs[s]);
        float w = fc_w[8 * s + gid];
        p_lo = fmaf(__low2float(hv),  w, p_lo);
        p_hi = fmaf(__high2float(hv), w, p_hi);
    }
#pragma unroll
    for (int off = 4; off < 32; off <<= 1) {
        p_lo += __shfl_xor_sync(0xFFFFFFFFu, p_lo, off);
        p_hi += __shfl_xor_sync(0xFFFFFFFFu, p_hi, off);
    }
    if (lane < 4) {
        float base = fc_b[0];
#pragma unroll
        for (int k = 0; k < 2; ++k) {
            long long r = rowbase + 2 * q + k;
            float s = (k ? p_hi : p_lo) + base;
            int mi = mat_idx[r], fi = freq_idx[r];
#pragma unroll
            for (int e = 0; e < 4; ++e) s += mat_emb[mi * 4 + e] * fc_w[32 + e];
#pragma unroll
            for (int e = 0; e < 2; ++e) s += freq_emb[fi * 2 + e] * fc_w[36 + e];
            out[r] = s;
        }
    }
}

extern "C" void kernel_launch(void* const* d_in, const int* in_sizes, int n_in,
                              void* d_out, int out_size) {
    const float* x        = (const float*)d_in[0];
    const int*   mat_idx  = (const int*)  d_in[1];
    const int*   freq_idx = (const int*)  d_in[2];
    const float* W_ih     = (const float*)d_in[3];
    const float* W_hh     = (const float*)d_in[4];
    const float* b_ih     = (const float*)d_in[5];
    const float* b_hh     = (const float*)d_in[6];
    const float* mat_emb  = (const float*)d_in[7];
    const float* freq_emb = (const float*)d_in[8];
    const float* fc_w     = (const float*)d_in[9];
    const float* fc_b     = (const float*)d_in[10];

    int B = in_sizes[1];                  // mat_idx has B elements
    int T = in_sizes[0] / (B * 3);        // x has B*T*3 elements
    int grid = B / 16;                    // 16 rows per CTA (2 warps x 8 rows)

    lstm_fused<<<grid, 64>>>(x, mat_idx, freq_idx, W_ih, W_hh, b_ih, b_hh,
                             mat_emb, freq_emb, fc_w, fc_b,
                             (float*)d_out, T);
}